// round 13
// baseline (speedup 1.0000x reference)
#include <cuda_runtime.h>
#include <cuda_pipeline.h>

// FilterLayer: y[b,c,h,w] = sum_{i,j in 5x5} xpad[b,c,h+i,w+j] * f[b,i*5+j,h,w]
// x: [4,3,512,512] f32, f: [4,25,512,512] f32, out: [4,3,512,512] f32, pad=2.
//
// R8: register-free in-flight bytes. f streamed via cp.async into an 8-slot
// per-tap smem ring (slot = 4KB = one tap row-tile), pipeline depth 6 ->
// ~96KB/SM in flight at 4 blocks/SM (vs ~33KB with register loads).
// Each thread cp.asyncs exactly the smem words it reads back -> per-thread
// __pipeline_wait_prior only, no extra barriers. x tile in smem as before.
// 2 px/thread, 512-thread blocks, __launch_bounds__(512,4).

#define Hc 512
#define Wc 512
#define Bc 4
#define WIN 5
#define PAD 2

#define TILE_W 128   // 64 threads x 2 px
#define TILE_H 8
#define SW (TILE_W + 2*PAD)   // 132
#define SH (TILE_H + 2*PAD)   // 12

#define X_FLOATS (3 * SH * SW)            // 4752
#define SLOT_FLOATS (TILE_H * TILE_W)     // 1024 floats = 4KB per tap
#define NSLOT 8
#define DEPTH 6                           // taps in flight
#define SMEM_BYTES ((X_FLOATS + NSLOT * SLOT_FLOATS) * 4)   // 51776

__global__ __launch_bounds__(512, 4)
void filter_kernel(const float* __restrict__ x,
                   const float* __restrict__ f,
                   float* __restrict__ out)
{
    extern __shared__ float smem[];
    float* sx = smem;               // [3][SH][SW]
    float* sf = smem + X_FLOATS;    // [NSLOT][TILE_H][TILE_W]

    const int tx = threadIdx.x;     // 0..63
    const int ty = threadIdx.y;     // 0..7
    const int tid = ty * 64 + tx;
    const int b  = blockIdx.z;
    const int h0 = blockIdx.y * TILE_H;
    const int w0 = blockIdx.x * TILE_W;

    const int h = h0 + ty;
    const int w = w0 + tx * 2;

    const float* fbase = f + ((long)(b * (WIN*WIN)) * Hc + h) * Wc + w;
    float* fslot_base = sf + ty * TILE_W + tx * 2;

    // ---- Prologue: issue cp.async for taps 0..DEPTH-1 (DRAM busy early) ----
    #pragma unroll
    for (int k = 0; k < DEPTH; k++) {
        __pipeline_memcpy_async(fslot_base + (k & (NSLOT - 1)) * SLOT_FLOATS,
                                fbase + (long)k * (Hc * Wc), 8);
        __pipeline_commit();
    }

    // ---- Stage x tile (with zero halo) into shared ----
    #pragma unroll 3
    for (int idx = tid; idx < X_FLOATS; idx += 512) {
        int c   = idx / (SH * SW);
        int rem = idx - c * (SH * SW);
        int r   = rem / SW;
        int col = rem - r * SW;
        int gh = h0 + r - PAD;
        int gw = w0 + col - PAD;
        float v = 0.0f;
        if ((unsigned)gh < Hc && (unsigned)gw < Wc)
            v = x[((b * 3 + c) * Hc + gh) * Wc + gw];
        sx[(c * SH + r) * SW + col] = v;
    }
    __syncthreads();

    float acc[3][2];
    #pragma unroll
    for (int c = 0; c < 3; c++) {
        acc[c][0] = 0.0f;
        acc[c][1] = 0.0f;
    }

    #pragma unroll
    for (int i = 0; i < WIN; i++) {
        // All 3 channels' 6-wide x windows for this tap row
        float xr[3][6];
        #pragma unroll
        for (int c = 0; c < 3; c++) {
            const float* row = sx + ((c * SH) + ty + i) * SW + tx * 2;
            const float2 a0 = *reinterpret_cast<const float2*>(row);
            const float2 a1 = *reinterpret_cast<const float2*>(row + 2);
            const float2 a2 = *reinterpret_cast<const float2*>(row + 4);
            xr[c][0] = a0.x; xr[c][1] = a0.y;
            xr[c][2] = a1.x; xr[c][3] = a1.y;
            xr[c][4] = a2.x; xr[c][5] = a2.y;
        }

        #pragma unroll
        for (int j = 0; j < WIN; j++) {
            const int k = i * WIN + j;

            // Issue tap k+DEPTH (its ring slot's old occupant k+DEPTH-8 was
            // consumed at least 2 iterations ago).
            if (k + DEPTH < WIN * WIN) {
                __pipeline_memcpy_async(
                    fslot_base + ((k + DEPTH) & (NSLOT - 1)) * SLOT_FLOATS,
                    fbase + (long)(k + DEPTH) * (Hc * Wc), 8);
                __pipeline_commit();
            }

            // Wait until tap k's group has landed. Groups issued so far =
            // min(k+DEPTH+1, 25); allow pending = issued - (k+1).
            __pipeline_wait_prior((k + DEPTH < WIN * WIN) ? DEPTH : (WIN * WIN - 1 - k));

            const float2 fv = *reinterpret_cast<const float2*>(
                fslot_base + (k & (NSLOT - 1)) * SLOT_FLOATS);

            #pragma unroll
            for (int c = 0; c < 3; c++) {
                acc[c][0] = fmaf(xr[c][0 + j], fv.x, acc[c][0]);
                acc[c][1] = fmaf(xr[c][1 + j], fv.y, acc[c][1]);
            }
        }
    }

    #pragma unroll
    for (int c = 0; c < 3; c++) {
        float2 o;
        o.x = acc[c][0];
        o.y = acc[c][1];
        __stcs(reinterpret_cast<float2*>(out + ((long)(b * 3 + c) * Hc + h) * Wc + w), o);
    }
}

extern "C" void kernel_launch(void* const* d_in, const int* in_sizes, int n_in,
                              void* d_out, int out_size)
{
    const float* x = (const float*)d_in[0];
    const float* f = (const float*)d_in[1];
    float* out = (float*)d_out;

    cudaFuncSetAttribute(filter_kernel,
                         cudaFuncAttributeMaxDynamicSharedMemorySize, SMEM_BYTES);

    dim3 block(64, 8, 1);
    dim3 grid(Wc / TILE_W, Hc / TILE_H, Bc);
    filter_kernel<<<grid, block, SMEM_BYTES>>>(x, f, out);
}

// round 15
// speedup vs baseline: 1.1174x; 1.1174x over previous
#include <cuda_runtime.h>
#include <cstdint>

// FilterLayer: y[b,c,h,w] = sum_{i,j in 5x5} xpad[b,c,h+i,w+j] * f[b,i*5+j,h,w]
// x: [4,3,512,512] f32, f: [4,25,512,512] f32, out: [4,3,512,512] f32, pad=2.
//
// R9: f streamed by the TMA/bulk-copy engine (cp.async.bulk -> UBLKCP), not
// per-thread loads. One thread issues 8x512B bulk copies per tap into an
// 8-slot smem ring (4KB/slot), mbarrier expect_tx completion, depth 6.
// Consumers: mbarrier parity wait + one LDS.64 per tap. Per-warp elected
// arrives recycle slots. Compute body = R7 (2px/thread, 64 warps, 32 regs).

#define Hc 512
#define Wc 512
#define Bc 4
#define WIN 5
#define WIN2 25
#define PAD 2

#define TILE_W 128   // 64 threads x 2 px
#define TILE_H 8
#define SW (TILE_W + 2*PAD)   // 132
#define SH (TILE_H + 2*PAD)   // 12

#define X_FLOATS (3 * SH * SW)          // 4752 floats = 19008 B
#define SF_OFF 4864                     // floats; byte 19456 (256B aligned)
#define SLOT_FLOATS (TILE_H * TILE_W)   // 1024 floats = 4096 B
#define NSLOT 8
#define DEPTH 6
#define MBAR_OFF 52224                  // bytes: 19456 + 8*4096
#define SMEM_BYTES 52480                // + 2*8*8 mbarriers + pad

__device__ __forceinline__ uint32_t smem_u32(const void* p) {
    uint32_t a;
    asm("{ .reg .u64 t; cvta.to.shared.u64 t, %1; cvt.u32.u64 %0, t; }"
        : "=r"(a) : "l"(p));
    return a;
}
__device__ __forceinline__ void mbar_init(uint32_t mb, uint32_t cnt) {
    asm volatile("mbarrier.init.shared.b64 [%0], %1;" :: "r"(mb), "r"(cnt) : "memory");
}
__device__ __forceinline__ void mbar_expect_tx(uint32_t mb, uint32_t bytes) {
    asm volatile("mbarrier.arrive.expect_tx.shared.b64 _, [%0], %1;"
                 :: "r"(mb), "r"(bytes) : "memory");
}
__device__ __forceinline__ void mbar_arrive(uint32_t mb) {
    asm volatile("mbarrier.arrive.shared.b64 _, [%0];" :: "r"(mb) : "memory");
}
__device__ __forceinline__ void mbar_wait(uint32_t mb, uint32_t parity) {
    asm volatile(
        "{\n\t.reg .pred P;\n"
        "W1_%=:\n\t"
        "mbarrier.try_wait.parity.acquire.cta.shared::cta.b64 P, [%0], %1, 0x989680;\n\t"
        "@P bra W2_%=;\n\t"
        "bra W1_%=;\n"
        "W2_%=:\n\t}"
        :: "r"(mb), "r"(parity) : "memory");
}
__device__ __forceinline__ void bulk_cp(uint32_t dst, const void* src,
                                        uint32_t bytes, uint32_t mb) {
    asm volatile(
        "cp.async.bulk.shared::cluster.global.mbarrier::complete_tx::bytes "
        "[%0], [%1], %2, [%3];"
        :: "r"(dst), "l"(src), "r"(bytes), "r"(mb) : "memory");
}

__global__ __launch_bounds__(512, 4)
void filter_kernel(const float* __restrict__ x,
                   const float* __restrict__ f,
                   float* __restrict__ out)
{
    extern __shared__ float smem[];
    float* sx = smem;               // [3][SH][SW]
    float* sf = smem + SF_OFF;      // [NSLOT][TILE_H][TILE_W]

    const int tx = threadIdx.x;     // 0..63
    const int ty = threadIdx.y;     // 0..7
    const int tid = ty * 64 + tx;
    const int b  = blockIdx.z;
    const int h0 = blockIdx.y * TILE_H;
    const int w0 = blockIdx.x * TILE_W;

    const uint32_t smem_base = smem_u32(smem);
    const uint32_t sf_base   = smem_base + SF_OFF * 4;
    const uint32_t full_mb   = smem_base + MBAR_OFF;        // 8 x u64
    const uint32_t empty_mb  = smem_base + MBAR_OFF + 64;   // 8 x u64

    // ---- Init barriers, then prologue bulk copies (taps 0..DEPTH-1) ----
    if (tid == 0) {
        #pragma unroll
        for (int s = 0; s < NSLOT; s++) {
            mbar_init(full_mb  + s * 8, 1);    // 1 arrive (expect_tx) + tx
            mbar_init(empty_mb + s * 8, 16);   // one elected arrive per warp
        }
        asm volatile("fence.proxy.async.shared::cta;" ::: "memory");

        #pragma unroll
        for (int m = 0; m < DEPTH; m++) {
            const uint32_t fb = full_mb + (m & 7) * 8;
            mbar_expect_tx(fb, TILE_H * TILE_W * 4);
            const float* src = f + (((long)(b * WIN2 + m)) * Hc + h0) * Wc + w0;
            const uint32_t dst = sf_base + (m & 7) * (SLOT_FLOATS * 4);
            #pragma unroll
            for (int r = 0; r < TILE_H; r++)
                bulk_cp(dst + r * (TILE_W * 4), src + (long)r * Wc, TILE_W * 4, fb);
        }
    }

    // ---- Stage x tile (with zero halo) into shared; overlaps bulk copies ----
    #pragma unroll 3
    for (int idx = tid; idx < X_FLOATS; idx += 512) {
        int c   = idx / (SH * SW);
        int rem = idx - c * (SH * SW);
        int r   = rem / SW;
        int col = rem - r * SW;
        int gh = h0 + r - PAD;
        int gw = w0 + col - PAD;
        float v = 0.0f;
        if ((unsigned)gh < Hc && (unsigned)gw < Wc)
            v = x[((b * 3 + c) * Hc + gh) * Wc + gw];
        sx[(c * SH + r) * SW + col] = v;
    }
    __syncthreads();   // x tile + barrier-inits visible to all

    const int h = h0 + ty;
    const int w = w0 + tx * 2;

    float acc[3][2];
    #pragma unroll
    for (int c = 0; c < 3; c++) { acc[c][0] = 0.0f; acc[c][1] = 0.0f; }

    const uint32_t frd = sf_base + (ty * TILE_W + tx * 2) * 4;

    #pragma unroll
    for (int i = 0; i < WIN; i++) {
        // All 3 channels' 6-wide x windows for this tap row
        float xr[3][6];
        #pragma unroll
        for (int c = 0; c < 3; c++) {
            const float* row = sx + ((c * SH) + ty + i) * SW + tx * 2;
            const float2 a0 = *reinterpret_cast<const float2*>(row);
            const float2 a1 = *reinterpret_cast<const float2*>(row + 2);
            const float2 a2 = *reinterpret_cast<const float2*>(row + 4);
            xr[c][0] = a0.x; xr[c][1] = a0.y;
            xr[c][2] = a1.x; xr[c][3] = a1.y;
            xr[c][4] = a2.x; xr[c][5] = a2.y;
        }

        #pragma unroll
        for (int j = 0; j < WIN; j++) {
            const int k = i * WIN + j;

            // Producer: issue tap k+DEPTH (recycling its ring slot)
            if (tid == 0) {
                const int m = k + DEPTH;
                if (m < WIN2) {
                    if (m >= NSLOT)
                        mbar_wait(empty_mb + (m & 7) * 8, ((m >> 3) - 1) & 1);
                    const uint32_t fb = full_mb + (m & 7) * 8;
                    mbar_expect_tx(fb, TILE_H * TILE_W * 4);
                    const float* src = f + (((long)(b * WIN2 + m)) * Hc + h0) * Wc + w0;
                    const uint32_t dst = sf_base + (m & 7) * (SLOT_FLOATS * 4);
                    #pragma unroll
                    for (int r = 0; r < TILE_H; r++)
                        bulk_cp(dst + r * (TILE_W * 4), src + (long)r * Wc,
                                TILE_W * 4, fb);
                }
            }

            // Consumer: wait tap k, read, FMA, release slot
            mbar_wait(full_mb + (k & 7) * 8, (k >> 3) & 1);

            float2 fv;
            asm volatile("ld.shared.v2.f32 {%0, %1}, [%2];"
                         : "=f"(fv.x), "=f"(fv.y)
                         : "r"(frd + (uint32_t)((k & 7) * (SLOT_FLOATS * 4))));

            #pragma unroll
            for (int c = 0; c < 3; c++) {
                acc[c][0] = fmaf(xr[c][0 + j], fv.x, acc[c][0]);
                acc[c][1] = fmaf(xr[c][1 + j], fv.y, acc[c][1]);
            }

            if ((tid & 31) == 0)
                mbar_arrive(empty_mb + (k & 7) * 8);
        }
    }

    #pragma unroll
    for (int c = 0; c < 3; c++) {
        float2 o;
        o.x = acc[c][0];
        o.y = acc[c][1];
        __stcs(reinterpret_cast<float2*>(out + ((long)(b * 3 + c) * Hc + h) * Wc + w), o);
    }
}

extern "C" void kernel_launch(void* const* d_in, const int* in_sizes, int n_in,
                              void* d_out, int out_size)
{
    const float* x = (const float*)d_in[0];
    const float* f = (const float*)d_in[1];
    float* out = (float*)d_out;

    cudaFuncSetAttribute(filter_kernel,
                         cudaFuncAttributeMaxDynamicSharedMemorySize, SMEM_BYTES);

    dim3 block(64, 8, 1);
    dim3 grid(Wc / TILE_W, Hc / TILE_H, Bc);
    filter_kernel<<<grid, block, SMEM_BYTES>>>(x, f, out);
}

// round 16
// speedup vs baseline: 1.4828x; 1.3269x over previous
#include <cuda_runtime.h>
#include <cuda_bf16.h>

// FilterLayer: y[b,c,h,w] = sum_{i,j in 5x5} xpad[b,c,h+i,w+j] * f[b,i*5+j,h,w]
// x: [4,3,512,512] f32, f: [4,25,512,512] f32, out: [4,3,512,512] f32, pad=2.
//
// R10: persistent grid-stride version of the R7 champion. Grid = 592 blocks
// (= 148 SMs x 4 resident), each block processes 1-2 of the 1024 tiles
// (q, q+592). Kills the 1.73-wave tail that capped DRAM at ~62%.
// Body unchanged: 2px/thread, 512-thread blocks, 32-reg cap, 19KB smem
// x-tile, __ldcs(f)/__stcs(out).

#define Hc 512
#define Wc 512
#define Bc 4
#define WIN 5
#define PAD 2

#define TILE_W 128   // 64 threads x 2 px
#define TILE_H 8
#define SW (TILE_W + 2*PAD)   // 132
#define SH (TILE_H + 2*PAD)   // 12

#define TILES_X (Wc / TILE_W)             // 4
#define TILES_Y (Hc / TILE_H)             // 64
#define TILES_PER_B (TILES_X * TILES_Y)   // 256
#define NTILES (TILES_PER_B * Bc)         // 1024
#define NBLOCKS 592                       // 148 SMs x 4 blocks

__global__ __launch_bounds__(512, 4)
void filter_kernel(const float* __restrict__ x,
                   const float* __restrict__ f,
                   float* __restrict__ out)
{
    __shared__ float sx[3][SH][SW];   // 19008 B

    const int tx = threadIdx.x;       // 0..63
    const int ty = threadIdx.y;       // 0..7
    const int tid = ty * 64 + tx;

    for (int q = blockIdx.x; q < NTILES; q += NBLOCKS) {
        const int b   = q >> 8;                    // / TILES_PER_B
        const int rem = q & 255;
        const int h0 = (rem >> 2) * TILE_H;        // / TILES_X
        const int w0 = (rem & 3)  * TILE_W;

        // ---- Stage x tile (with zero halo) into shared ----
        const int total = 3 * SH * SW;    // 4752
        #pragma unroll 3
        for (int idx = tid; idx < total; idx += 512) {
            int c   = idx / (SH * SW);
            int r2  = idx - c * (SH * SW);
            int r   = r2 / SW;
            int col = r2 - r * SW;
            int gh = h0 + r - PAD;
            int gw = w0 + col - PAD;
            float v = 0.0f;
            if ((unsigned)gh < Hc && (unsigned)gw < Wc)
                v = x[((b * 3 + c) * Hc + gh) * Wc + gw];
            sx[c][r][col] = v;
        }
        __syncthreads();

        const int h = h0 + ty;
        const int w = w0 + tx * 2;

        float acc[3][2];
        #pragma unroll
        for (int c = 0; c < 3; c++) { acc[c][0] = 0.0f; acc[c][1] = 0.0f; }

        const float* fbase = f + ((long)(b * (WIN*WIN)) * Hc + h) * Wc + w;

        #pragma unroll
        for (int i = 0; i < WIN; i++) {
            // All 3 channels' 6-wide x windows for this tap row
            float xr[3][6];
            #pragma unroll
            for (int c = 0; c < 3; c++) {
                const float* row = &sx[c][ty + i][tx * 2];
                const float2 a0 = *reinterpret_cast<const float2*>(row);
                const float2 a1 = *reinterpret_cast<const float2*>(row + 2);
                const float2 a2 = *reinterpret_cast<const float2*>(row + 4);
                xr[c][0] = a0.x; xr[c][1] = a0.y;
                xr[c][2] = a1.x; xr[c][3] = a1.y;
                xr[c][4] = a2.x; xr[c][5] = a2.y;
            }

            #pragma unroll
            for (int j = 0; j < WIN; j++) {
                const float2 fv = __ldcs(reinterpret_cast<const float2*>(
                                      fbase + (long)(i * WIN + j) * (Hc * Wc)));
                #pragma unroll
                for (int c = 0; c < 3; c++) {
                    acc[c][0] = fmaf(xr[c][0 + j], fv.x, acc[c][0]);
                    acc[c][1] = fmaf(xr[c][1 + j], fv.y, acc[c][1]);
                }
            }
        }

        #pragma unroll
        for (int c = 0; c < 3; c++) {
            float2 o;
            o.x = acc[c][0];
            o.y = acc[c][1];
            __stcs(reinterpret_cast<float2*>(
                out + ((long)(b * 3 + c) * Hc + h) * Wc + w), o);
        }

        // Protect smem before next iteration's staging overwrites it.
        __syncthreads();
    }
}

extern "C" void kernel_launch(void* const* d_in, const int* in_sizes, int n_in,
                              void* d_out, int out_size)
{
    const float* x = (const float*)d_in[0];
    const float* f = (const float*)d_in[1];
    float* out = (float*)d_out;

    dim3 block(64, 8, 1);
    dim3 grid(NBLOCKS, 1, 1);
    filter_kernel<<<grid, block>>>(x, f, out);
}